// round 14
// baseline (speedup 1.0000x reference)
#include <cuda_runtime.h>

// QuadratureFunction: per-cell DOF gather (3 vertex + 3x2 edge w/ orientation
// flip + 1 face) contracted against y[C, NB=10, Q=16] -> out[C, Q=16].
//
// Steady-state DRAM traffic per graph replay: y (320MB, __ldcs) + out (32MB,
// __stcs) = 352MB. Indices + dof arrays (27MB) stay L2-resident across
// replays (validated R4 vs R6). Flat launch (persistent grid regressed R12).
//
// Evidence so far: DRAM% pinned at ~79% for occ 66-89% and regs 32-40
// (R11: 32regs/85%occ/54.0us; R13: 40regs/66%occ/53.8us). R14 probes the
// interior of the occ x MLP tradeoff: __launch_bounds__(256, 7) -> <=36
// regs, 7 blocks/SM (1792 thr, 87.5% occ) with ~8/10 y-loads batched.
// If flat, ~79% DRAM SOL is the mixed-stream HBM floor and we stop.

#define NB 10
#define Q  16

__global__ __launch_bounds__(256, 7)
void quad_kernel(const float* __restrict__ vertex_dofs,
                 const float* __restrict__ edge_dofs,
                 const float* __restrict__ face_dofs,
                 const float* __restrict__ y,
                 const int*   __restrict__ faces,
                 const int*   __restrict__ faces_to_edges,
                 const int*   __restrict__ edge_orientation,
                 float*       __restrict__ out,
                 int C)
{
    int t = blockIdx.x * blockDim.x + threadIdx.x;
    int c  = t >> 2;            // cell index (4 threads per cell)
    int q0 = (t & 3) << 2;      // starting quadrature point (0,4,8,12)
    if (c >= C) return;

    // --- issue the 10 streaming y loads up front (max MLP within regs) ---
    const float4* yb = reinterpret_cast<const float4*>(
        y + (size_t)c * (NB * Q) + q0);

    float4 yv[NB];
    #pragma unroll
    for (int b = 0; b < NB; b++)
        yv[b] = __ldcs(&yb[b * (Q / 4)]);   // evict-first: no L2 pollution

    // --- gather local dofs (default-cached: L2-persistent across graph
    //     replays). Duplicate addresses within the 4 lanes of a cell
    //     coalesce to a single transaction. ---
    float dofs[NB];

    int v0 = faces[3 * c + 0];
    int v1 = faces[3 * c + 1];
    int v2 = faces[3 * c + 2];
    dofs[0] = vertex_dofs[v0];   // DV = 1
    dofs[1] = vertex_dofs[v1];
    dofs[2] = vertex_dofs[v2];

    #pragma unroll
    for (int e = 0; e < 3; e++) {
        int ei = faces_to_edges[3 * c + e];
        int o  = edge_orientation[3 * c + e];
        // DE = 2: keep order when o==1, flip when o==0
        float d0 = edge_dofs[2 * ei + 0];
        float d1 = edge_dofs[2 * ei + 1];
        dofs[3 + 2 * e + 0] = o ? d0 : d1;
        dofs[3 + 2 * e + 1] = o ? d1 : d0;
    }

    dofs[9] = face_dofs[c];      // DF = 1

    // --- contraction: out[c, q0..q0+3] = sum_b dofs[b] * y[c, b, q0..q0+3] ---
    float4 acc = make_float4(0.f, 0.f, 0.f, 0.f);
    #pragma unroll
    for (int b = 0; b < NB; b++) {
        acc.x = fmaf(dofs[b], yv[b].x, acc.x);
        acc.y = fmaf(dofs[b], yv[b].y, acc.y);
        acc.z = fmaf(dofs[b], yv[b].z, acc.z);
        acc.w = fmaf(dofs[b], yv[b].w, acc.w);
    }

    __stcs(reinterpret_cast<float4*>(out + (size_t)c * Q + q0), acc);
}

extern "C" void kernel_launch(void* const* d_in, const int* in_sizes, int n_in,
                              void* d_out, int out_size)
{
    const float* vertex_dofs      = (const float*)d_in[0];
    const float* edge_dofs        = (const float*)d_in[1];
    const float* face_dofs        = (const float*)d_in[2];
    const float* y                = (const float*)d_in[3];
    const int*   faces            = (const int*)d_in[4];
    const int*   faces_to_edges   = (const int*)d_in[5];
    const int*   edge_orientation = (const int*)d_in[6];
    float*       out              = (float*)d_out;

    int C = in_sizes[2];               // face_dofs has C*DF = C elements
    int total_threads = C * 4;         // 4 threads per cell
    int block = 256;
    int grid = (total_threads + block - 1) / block;

    quad_kernel<<<grid, block>>>(vertex_dofs, edge_dofs, face_dofs, y,
                                 faces, faces_to_edges, edge_orientation,
                                 out, C);
}

// round 16
// speedup vs baseline: 1.0255x; 1.0255x over previous
#include <cuda_runtime.h>

// QuadratureFunction: per-cell DOF gather (3 vertex + 3x2 edge w/ orientation
// flip + 1 face) contracted against y[C, NB=10, Q=16] -> out[C, Q=16].
//
// Steady-state DRAM traffic per graph replay: y (320MB, __ldcs) + out (32MB,
// __stcs) = 352MB; indices + dof arrays (27MB) stay L2-resident across
// replays (validated R4 vs R6). Flat launch (persistent grid regressed R12).
//
// occ x MLP sweep complete (R11/R12/R13/R14): DRAM pinned at 78-79.5% SOL
// (~6.3TB/s) across occ 66-89% and regs 32-40 -> that is the device ceiling
// for this mixed 10:1 R/W stream. Best corner: block=256, bounds(256,6),
// 40 regs (R13, 53.8us).
//
// R15: same config; issue the DEPENDENT gather chain (index -> dof, ~2x L2
// latency serial) before the independent y burst so the longest latency
// chain starts first and hides fully under the y stream.

#define NB 10
#define Q  16

__global__ __launch_bounds__(256, 6)
void quad_kernel(const float* __restrict__ vertex_dofs,
                 const float* __restrict__ edge_dofs,
                 const float* __restrict__ face_dofs,
                 const float* __restrict__ y,
                 const int*   __restrict__ faces,
                 const int*   __restrict__ faces_to_edges,
                 const int*   __restrict__ edge_orientation,
                 float*       __restrict__ out,
                 int C)
{
    int t = blockIdx.x * blockDim.x + threadIdx.x;
    int c  = t >> 2;            // cell index (4 threads per cell)
    int q0 = (t & 3) << 2;      // starting quadrature point (0,4,8,12)
    if (c >= C) return;

    // --- start the dependent gather chain FIRST (idx -> dof: two serial
    //     L2-latency hops, the longest chain in the kernel). Duplicate
    //     addresses within the 4 lanes of a cell coalesce for free. ---
    int v0 = faces[3 * c + 0];
    int v1 = faces[3 * c + 1];
    int v2 = faces[3 * c + 2];

    int ei0 = faces_to_edges[3 * c + 0];
    int ei1 = faces_to_edges[3 * c + 1];
    int ei2 = faces_to_edges[3 * c + 2];
    int o0  = edge_orientation[3 * c + 0];
    int o1  = edge_orientation[3 * c + 1];
    int o2  = edge_orientation[3 * c + 2];

    // --- independent streaming y burst (fills the latency shadow) ---
    const float4* yb = reinterpret_cast<const float4*>(
        y + (size_t)c * (NB * Q) + q0);

    float4 yv[NB];
    #pragma unroll
    for (int b = 0; b < NB; b++)
        yv[b] = __ldcs(&yb[b * (Q / 4)]);   // evict-first: no L2 pollution

    // --- second hop of the gather chain + face dof ---
    float dofs[NB];
    dofs[0] = vertex_dofs[v0];   // DV = 1
    dofs[1] = vertex_dofs[v1];
    dofs[2] = vertex_dofs[v2];

    float e0a = edge_dofs[2 * ei0 + 0], e0b = edge_dofs[2 * ei0 + 1];
    float e1a = edge_dofs[2 * ei1 + 0], e1b = edge_dofs[2 * ei1 + 1];
    float e2a = edge_dofs[2 * ei2 + 0], e2b = edge_dofs[2 * ei2 + 1];

    // DE = 2: keep order when o==1, flip when o==0
    dofs[3] = o0 ? e0a : e0b;  dofs[4] = o0 ? e0b : e0a;
    dofs[5] = o1 ? e1a : e1b;  dofs[6] = o1 ? e1b : e1a;
    dofs[7] = o2 ? e2a : e2b;  dofs[8] = o2 ? e2b : e2a;

    dofs[9] = face_dofs[c];      // DF = 1

    // --- contraction: out[c, q0..q0+3] = sum_b dofs[b] * y[c, b, q0..q0+3] ---
    float4 acc = make_float4(0.f, 0.f, 0.f, 0.f);
    #pragma unroll
    for (int b = 0; b < NB; b++) {
        acc.x = fmaf(dofs[b], yv[b].x, acc.x);
        acc.y = fmaf(dofs[b], yv[b].y, acc.y);
        acc.z = fmaf(dofs[b], yv[b].z, acc.z);
        acc.w = fmaf(dofs[b], yv[b].w, acc.w);
    }

    __stcs(reinterpret_cast<float4*>(out + (size_t)c * Q + q0), acc);
}

extern "C" void kernel_launch(void* const* d_in, const int* in_sizes, int n_in,
                              void* d_out, int out_size)
{
    const float* vertex_dofs      = (const float*)d_in[0];
    const float* edge_dofs        = (const float*)d_in[1];
    const float* face_dofs        = (const float*)d_in[2];
    const float* y                = (const float*)d_in[3];
    const int*   faces            = (const int*)d_in[4];
    const int*   faces_to_edges   = (const int*)d_in[5];
    const int*   edge_orientation = (const int*)d_in[6];
    float*       out              = (float*)d_out;

    int C = in_sizes[2];               // face_dofs has C*DF = C elements
    int total_threads = C * 4;         // 4 threads per cell
    int block = 256;
    int grid = (total_threads + block - 1) / block;

    quad_kernel<<<grid, block>>>(vertex_dofs, edge_dofs, face_dofs, y,
                                 faces, faces_to_edges, edge_orientation,
                                 out, C);
}